// round 7
// baseline (speedup 1.0000x reference)
#include <cuda_runtime.h>
#include <cstdint>

// RoIAlign (TF crop_and_resize) — cp.async double-buffered, demand-sized patches,
// 128-channel slabs, templated copy-slot count.
// featuremap: (N=2,C=256,H=200,W=304) f32; rois: (M,5); out: (M,256,7,7) f32.
//
// grid = (M, 2): block = (box m, 128-channel slab). warp = channel worker
// (16 channels, stride 8). Per channel, stage only rows/cols the box's 7x7
// bilinear taps need: nrows = yhi-ys+1 (<=16), cols in {8,16,20}.

#define CROP 7
#define NPTS 49
#define C_CH 256
#define H_IM 200
#define W_IM 304
#define PLANE (H_IM * W_IM)
#define SSTRIDE 20                 // smem row stride (floats)
#define PATCH (16 * SSTRIDE)       // 320 floats
#define CH_PER_BLK 128
#define CH_PER_WARP 16

__device__ __forceinline__ void cp16(unsigned int dst, const float* src) {
    asm volatile("cp.async.cg.shared.global [%0], [%1], 16;\n"
                 :: "r"(dst), "l"(src));
}
__device__ __forceinline__ void cp_commit() {
    asm volatile("cp.async.commit_group;\n" ::: "memory");
}
template <int N>
__device__ __forceinline__ void cp_wait() {
    asm volatile("cp.async.wait_group %0;\n" :: "n"(N) : "memory");
}

struct TapParams {
    int   off_tl[2], off_tr[2], off_bl[2], off_br[2];
    float xlp[2], ylp[2];
    bool  val[2];
};

// NC4 = float4 chunks per row (2/4/5 -> 8/16/20 cols). SLOTS = ceil(16*NC4/32).
template <int NC4, int SLOTS>
__device__ __forceinline__ void run_channels(
    const float* __restrict__ base,   // img + n*C*PLANE + ys*W + xs
    float* __restrict__ out_m,        // out + m*256*49
    float* __restrict__ sbuf,         // this warp's 2*PATCH floats
    unsigned int sbuf_sh,
    int c_first, int lane, int nchunk,
    const TapParams& tp)
{
    int g_off[SLOTS], s_off[SLOTS];
    bool ok[SLOTS];
    #pragma unroll
    for (int t = 0; t < SLOTS; ++t) {
        const int e = t * 32 + lane;
        ok[t] = (e < nchunk);
        const int r  = e / NC4;
        const int c4 = e % NC4;
        g_off[t] = r * W_IM + c4 * 4;
        s_off[t] = (r * SSTRIDE + c4 * 4) * 4;   // bytes
    }

    // prologue: channel 0 -> buf 0
    {
        const float* pc = base + (size_t)c_first * PLANE;
        #pragma unroll
        for (int t = 0; t < SLOTS; ++t)
            if (ok[t]) cp16(sbuf_sh + s_off[t], pc + g_off[t]);
        cp_commit();
    }

    #pragma unroll
    for (int k = 0; k < CH_PER_WARP; ++k) {
        const int c = c_first + k * 8;

        if (k + 1 < CH_PER_WARP) {
            const float* pc = base + (size_t)(c + 8) * PLANE;
            const unsigned int db = sbuf_sh + (unsigned int)(((k + 1) & 1) * (PATCH * 4));
            #pragma unroll
            for (int t = 0; t < SLOTS; ++t)
                if (ok[t]) cp16(db + s_off[t], pc + g_off[t]);
            cp_commit();
            cp_wait<1>();
        } else {
            cp_wait<0>();
        }
        __syncwarp();

        const float* patch = sbuf + (k & 1) * PATCH;
        float* __restrict__ op = out_m + (size_t)c * NPTS;
        #pragma unroll
        for (int t = 0; t < 2; ++t) {
            const int p = lane + t * 32;
            if (p < NPTS) {
                float v = 0.0f;
                if (tp.val[t]) {
                    const float tl = patch[tp.off_tl[t]];
                    const float tr = patch[tp.off_tr[t]];
                    const float bl = patch[tp.off_bl[t]];
                    const float br = patch[tp.off_br[t]];
                    const float top = fmaf(tr - tl, tp.xlp[t], tl);
                    const float bot = fmaf(br - bl, tp.xlp[t], bl);
                    v = fmaf(bot - top, tp.ylp[t], top);
                }
                op[p] = v;
            }
        }
        __syncwarp();
    }
}

__global__ void __launch_bounds__(256)
roialign6_kernel(const float* __restrict__ img,
                 const float* __restrict__ rois,
                 const float* __restrict__ scale_p,
                 float* __restrict__ out,
                 int M)
{
    __shared__ __align__(16) float s_patch[8 * 2 * PATCH];   // 20.5 KB

    const int m    = blockIdx.x;
    const int cg   = blockIdx.y;            // channel group (0..1)
    const int tid  = threadIdx.x;
    const int wid  = tid >> 5;
    const int lane = tid & 31;
    if (m >= M) return;

    // ---- block-uniform ROI params ----
    const float scale = *scale_p;
    const float* roi = rois + (size_t)m * 5;
    const int   n   = (int)roi[0];
    const float x1s = roi[1] * scale;
    const float y1s = roi[2] * scale;
    const float sw  = (roi[3] * scale - x1s) * (1.0f / CROP);
    const float sh  = (roi[4] * scale - y1s) * (1.0f / CROP);
    const float xb  = x1s + sw * 0.5f - 0.5f;
    const float yb  = y1s + sh * 0.5f - 0.5f;

    // y extent actually needed by the taps
    const int ylo = min(max((int)floorf(yb), 0), H_IM - 1);
    const int yhi = min(max((int)ceilf(yb + 6.0f * sh), 0), H_IM - 1);
    const int ys  = min(ylo, H_IM - 16);
    const int nrows = yhi - ys + 1;                       // <= 16

    // x extent and column-path selection
    const int xlo = min(max((int)floorf(xb), 0), W_IM - 1);
    const int xhi = min(max((int)ceilf(xb + 6.0f * sw), 0), W_IM - 1);
    const int xs8  = min(xlo & ~3, W_IM - 8);
    const int xs16 = min(xlo & ~3, W_IM - 16);
    const int path = ((xhi - xs8) <= 7) ? 0 : ((xhi - xs16) <= 15 ? 1 : 2);
    const int xs   = (path == 0) ? xs8 : (path == 1) ? xs16
                                       : min(xlo & ~3, W_IM - 20);

    // ---- per-lane tap params (points p = lane, lane+32) ----
    TapParams tp;
    #pragma unroll
    for (int t = 0; t < 2; ++t) {
        const int p = lane + t * 32;
        const int pi = (p < NPTS) ? p : 0;
        const int i = pi / CROP;
        const int j = pi % CROP;
        const float x = xb + (float)j * sw;
        const float y = yb + (float)i * sh;
        const bool vy = (y >= 0.0f) && (y <= (float)(H_IM - 1));
        const bool vx = (x >= 0.0f) && (x <= (float)(W_IM - 1));
        const float yf = floorf(y);
        const float xf = floorf(x);
        const int yt = min(max((int)yf, 0), H_IM - 1) - ys;
        const int yB = min(max((int)ceilf(y), 0), H_IM - 1) - ys;
        const int xl = min(max((int)xf, 0), W_IM - 1) - xs;
        const int xr = min(max((int)ceilf(x), 0), W_IM - 1) - xs;
        tp.off_tl[t] = yt * SSTRIDE + xl;
        tp.off_tr[t] = yt * SSTRIDE + xr;
        tp.off_bl[t] = yB * SSTRIDE + xl;
        tp.off_br[t] = yB * SSTRIDE + xr;
        tp.ylp[t] = y - yf;
        tp.xlp[t] = x - xf;
        tp.val[t] = vx && vy && (p < NPTS);
    }

    const float* __restrict__ base =
        img + (size_t)n * C_CH * (size_t)PLANE + (size_t)(ys * W_IM + xs);
    float* __restrict__ out_m = out + (size_t)m * (C_CH * NPTS);

    float* sbuf = s_patch + wid * (2 * PATCH);
    const unsigned int sbuf_sh = (unsigned int)__cvta_generic_to_shared(sbuf);
    const int c_first = cg * CH_PER_BLK + wid;

    if (path == 0)
        run_channels<2, 1>(base, out_m, sbuf, sbuf_sh, c_first, lane, nrows * 2, tp);
    else if (path == 1)
        run_channels<4, 2>(base, out_m, sbuf, sbuf_sh, c_first, lane, nrows * 4, tp);
    else
        run_channels<5, 3>(base, out_m, sbuf, sbuf_sh, c_first, lane, nrows * 5, tp);
}

extern "C" void kernel_launch(void* const* d_in, const int* in_sizes, int n_in,
                              void* d_out, int out_size)
{
    const float* img   = (const float*)d_in[0];
    const float* rois  = (const float*)d_in[1];
    const float* scale = (const float*)d_in[2];
    float* out = (float*)d_out;

    const int M = in_sizes[1] / 5;
    dim3 grid(M, C_CH / CH_PER_BLK);
    roialign6_kernel<<<grid, 256>>>(img, rois, scale, out, M);
}

// round 8
// speedup vs baseline: 1.1732x; 1.1732x over previous
#include <cuda_runtime.h>
#include <cstdint>

// RoIAlign (TF crop_and_resize) — triple-buffered cp.async, 32B-sector-aligned
// demand-sized patches.
// featuremap: (N=2,C=256,H=200,W=304) f32; rois: (M,5); out: (M,256,7,7) f32.
//
// grid = (M, 4): block = (box m, 64-channel slab). warp = channel worker
// (8 channels, stride 8). Patch origin xs is 32B (8-float) aligned and the row
// stride (1216B) is 32B-divisible, so each staged row touches exactly
// {1,2,3} L2 sectors for the {8,16,24}-column paths. Rows fetched = only the
// nrows (<=16) the box's 7x7 bilinear taps need.

#define CROP 7
#define NPTS 49
#define C_CH 256
#define H_IM 200
#define W_IM 304
#define PLANE (H_IM * W_IM)
#define SSTRIDE 24                 // smem row stride (floats)
#define PATCH (16 * SSTRIDE)       // 384 floats
#define NBUF 3
#define CH_PER_BLK 64
#define CH_PER_WARP 8

__device__ __forceinline__ void cp16(unsigned int dst, const float* src) {
    asm volatile("cp.async.cg.shared.global [%0], [%1], 16;\n"
                 :: "r"(dst), "l"(src));
}
__device__ __forceinline__ void cp_commit() {
    asm volatile("cp.async.commit_group;\n" ::: "memory");
}
template <int N>
__device__ __forceinline__ void cp_wait() {
    asm volatile("cp.async.wait_group %0;\n" :: "n"(N) : "memory");
}

struct TapParams {
    int   off_tl[2], off_tr[2], off_bl[2], off_br[2];
    float xlp[2], ylp[2];
    bool  val[2];
};

// NC4 = float4 chunks per row (2/4/6 -> 8/16/24 cols). SLOTS = ceil(16*NC4/32).
template <int NC4, int SLOTS>
__device__ __forceinline__ void run_channels(
    const float* __restrict__ base,   // img + n*C*PLANE + ys*W + xs
    float* __restrict__ out_m,        // out + m*256*49
    float* __restrict__ sbuf,         // this warp's NBUF*PATCH floats
    unsigned int sbuf_sh,
    int c_first, int lane, int nchunk,
    const TapParams& tp)
{
    int g_off[SLOTS], s_off[SLOTS];
    bool ok[SLOTS];
    #pragma unroll
    for (int t = 0; t < SLOTS; ++t) {
        const int e = t * 32 + lane;
        ok[t] = (e < nchunk);
        const int r  = e / NC4;
        const int c4 = e % NC4;
        g_off[t] = r * W_IM + c4 * 4;
        s_off[t] = (r * SSTRIDE + c4 * 4) * 4;   // bytes
    }

    // prologue: issue channels 0 and 1 into buffers 0, 1
    #pragma unroll
    for (int s = 0; s < 2; ++s) {
        const float* pc = base + (size_t)(c_first + s * 8) * PLANE;
        const unsigned int db = sbuf_sh + (unsigned int)(s * (PATCH * 4));
        #pragma unroll
        for (int t = 0; t < SLOTS; ++t)
            if (ok[t]) cp16(db + s_off[t], pc + g_off[t]);
        cp_commit();
    }

    #pragma unroll
    for (int k = 0; k < CH_PER_WARP; ++k) {
        const int c = c_first + k * 8;

        if (k + 2 < CH_PER_WARP) {
            // issue channel k+2 into buffer (k+2)%3 (its readers finished at
            // end of iteration k-1, fenced by the trailing __syncwarp)
            const float* pc = base + (size_t)(c + 16) * PLANE;
            const unsigned int db =
                sbuf_sh + (unsigned int)(((k + 2) % NBUF) * (PATCH * 4));
            #pragma unroll
            for (int t = 0; t < SLOTS; ++t)
                if (ok[t]) cp16(db + s_off[t], pc + g_off[t]);
            cp_commit();
            cp_wait<2>();
        } else if (k + 1 < CH_PER_WARP) {
            cp_wait<1>();
        } else {
            cp_wait<0>();
        }
        __syncwarp();

        const float* patch = sbuf + (k % NBUF) * PATCH;
        float* __restrict__ op = out_m + (size_t)c * NPTS;
        #pragma unroll
        for (int t = 0; t < 2; ++t) {
            const int p = lane + t * 32;
            if (p < NPTS) {
                float v = 0.0f;
                if (tp.val[t]) {
                    const float tl = patch[tp.off_tl[t]];
                    const float tr = patch[tp.off_tr[t]];
                    const float bl = patch[tp.off_bl[t]];
                    const float br = patch[tp.off_br[t]];
                    const float top = fmaf(tr - tl, tp.xlp[t], tl);
                    const float bot = fmaf(br - bl, tp.xlp[t], bl);
                    v = fmaf(bot - top, tp.ylp[t], top);
                }
                op[p] = v;
            }
        }
        __syncwarp();
    }
}

__global__ void __launch_bounds__(256)
roialign8_kernel(const float* __restrict__ img,
                 const float* __restrict__ rois,
                 const float* __restrict__ scale_p,
                 float* __restrict__ out,
                 int M)
{
    __shared__ __align__(16) float s_patch[8 * NBUF * PATCH];   // 36 KB

    const int m    = blockIdx.x;
    const int cg   = blockIdx.y;            // channel group (0..3)
    const int tid  = threadIdx.x;
    const int wid  = tid >> 5;
    const int lane = tid & 31;
    if (m >= M) return;

    // ---- block-uniform ROI params ----
    const float scale = *scale_p;
    const float* roi = rois + (size_t)m * 5;
    const int   n   = (int)roi[0];
    const float x1s = roi[1] * scale;
    const float y1s = roi[2] * scale;
    const float sw  = (roi[3] * scale - x1s) * (1.0f / CROP);
    const float sh  = (roi[4] * scale - y1s) * (1.0f / CROP);
    const float xb  = x1s + sw * 0.5f - 0.5f;
    const float yb  = y1s + sh * 0.5f - 0.5f;

    // y extent actually needed by the taps
    const int ylo = min(max((int)floorf(yb), 0), H_IM - 1);
    const int yhi = min(max((int)ceilf(yb + 6.0f * sh), 0), H_IM - 1);
    const int ys  = min(ylo, H_IM - 16);
    const int nrows = yhi - ys + 1;                       // <= 16

    // x extent; 32B-aligned origin; column-path selection {8,16,24}
    const int xlo = min(max((int)floorf(xb), 0), W_IM - 1);
    const int xhi = min(max((int)ceilf(xb + 6.0f * sw), 0), W_IM - 1);
    const int xa   = xlo & ~7;                            // 32B aligned
    const int xs8  = min(xa, W_IM - 8);
    const int xs16 = min(xa, W_IM - 16);
    const int path = ((xhi - xs8) <= 7) ? 0 : ((xhi - xs16) <= 15 ? 1 : 2);
    const int xs   = (path == 0) ? xs8 : (path == 1) ? xs16
                                       : min(xa, W_IM - 24);

    // ---- per-lane tap params (points p = lane, lane+32) ----
    TapParams tp;
    #pragma unroll
    for (int t = 0; t < 2; ++t) {
        const int p = lane + t * 32;
        const int pi = (p < NPTS) ? p : 0;
        const int i = pi / CROP;
        const int j = pi % CROP;
        const float x = xb + (float)j * sw;
        const float y = yb + (float)i * sh;
        const bool vy = (y >= 0.0f) && (y <= (float)(H_IM - 1));
        const bool vx = (x >= 0.0f) && (x <= (float)(W_IM - 1));
        const float yf = floorf(y);
        const float xf = floorf(x);
        const int yt = min(max((int)yf, 0), H_IM - 1) - ys;
        const int yB = min(max((int)ceilf(y), 0), H_IM - 1) - ys;
        const int xl = min(max((int)xf, 0), W_IM - 1) - xs;
        const int xr = min(max((int)ceilf(x), 0), W_IM - 1) - xs;
        tp.off_tl[t] = yt * SSTRIDE + xl;
        tp.off_tr[t] = yt * SSTRIDE + xr;
        tp.off_bl[t] = yB * SSTRIDE + xl;
        tp.off_br[t] = yB * SSTRIDE + xr;
        tp.ylp[t] = y - yf;
        tp.xlp[t] = x - xf;
        tp.val[t] = vx && vy && (p < NPTS);
    }

    const float* __restrict__ base =
        img + (size_t)n * C_CH * (size_t)PLANE + (size_t)(ys * W_IM + xs);
    float* __restrict__ out_m = out + (size_t)m * (C_CH * NPTS);

    float* sbuf = s_patch + wid * (NBUF * PATCH);
    const unsigned int sbuf_sh = (unsigned int)__cvta_generic_to_shared(sbuf);
    const int c_first = cg * CH_PER_BLK + wid;

    if (path == 0)
        run_channels<2, 1>(base, out_m, sbuf, sbuf_sh, c_first, lane, nrows * 2, tp);
    else if (path == 1)
        run_channels<4, 2>(base, out_m, sbuf, sbuf_sh, c_first, lane, nrows * 4, tp);
    else
        run_channels<6, 3>(base, out_m, sbuf, sbuf_sh, c_first, lane, nrows * 6, tp);
}

extern "C" void kernel_launch(void* const* d_in, const int* in_sizes, int n_in,
                              void* d_out, int out_size)
{
    const float* img   = (const float*)d_in[0];
    const float* rois  = (const float*)d_in[1];
    const float* scale = (const float*)d_in[2];
    float* out = (float*)d_out;

    const int M = in_sizes[1] / 5;
    dim3 grid(M, C_CH / CH_PER_BLK);
    roialign8_kernel<<<grid, 256>>>(img, rois, scale, out, M);
}